// round 10
// baseline (speedup 1.0000x reference)
#include <cuda_runtime.h>
#include <cuda_bf16.h>
#include <mma.h>
#include <cstdint>

using namespace nvcuda;

#define NNODES 100000
#define HIDDIM 128
#define INDIM  256
#define MAXE   1600000
#define NF ((long)NNODES * HIDDIM)        // 12,800,000 floats per buffer

// Scratch (static device globals — no allocation allowed)
__device__ float4 g_scratch[3 * NF / 4];  // h1, z1, h2
__device__ int    g_deg[NNODES];
__device__ float  g_dinv[NNODES];
__device__ int    g_rowStart[NNODES + 1]; // CSR offsets (by target node)
__device__ int    g_cursor[NNODES];
__device__ int    g_src[MAXE];            // source node per CSR slot
__device__ int    g_blockSums[256];
// split-precision weights: W1(32768) | W2(16384) | Wp(16384)
__device__ __nv_bfloat16 g_whi[65536];
__device__ __nv_bfloat16 g_wlo[65536];

__device__ __forceinline__ float* scr(long off) {
    return reinterpret_cast<float*>(g_scratch) + off;
}

#define OFF_H1 ((long)0)
#define OFF_Z1 (NF)
#define OFF_H2 (2 * NF)
#define WOFF_W1 0
#define WOFF_W2 32768
#define WOFF_WP 49152

// ---------------------------------------------------------------------------
// degree / norm
// ---------------------------------------------------------------------------
__global__ void zero_deg_kernel(int n) {
    int i = blockIdx.x * blockDim.x + threadIdx.x;
    if (i < n) g_deg[i] = 0;
}

__global__ void count_deg_kernel(const int* __restrict__ ei, int E) {
    int e = blockIdx.x * blockDim.x + threadIdx.x;
    if (e < E) atomicAdd(&g_deg[ei[E + e]], 1);
}

__global__ void dinv_kernel(int n) {
    int i = blockIdx.x * blockDim.x + threadIdx.x;
    if (i < n) g_dinv[i] = rsqrtf((float)(g_deg[i] + 1));
}

// ---------------------------------------------------------------------------
// weight split: all three W -> hi + lo bf16 in one launch
// ---------------------------------------------------------------------------
__global__ void convert_w_kernel(const float* __restrict__ W1,
                                 const float* __restrict__ W2,
                                 const float* __restrict__ Wp) {
    int i = blockIdx.x * blockDim.x + threadIdx.x;   // 0..65535
    float v;
    if (i < 32768)       v = W1[i];
    else if (i < 49152)  v = W2[i - 32768];
    else                 v = Wp[i - 49152];
    __nv_bfloat16 hi = __float2bfloat16(v);
    __nv_bfloat16 lo = __float2bfloat16(v - __bfloat162float(hi));
    g_whi[i] = hi;
    g_wlo[i] = lo;
}

// ---------------------------------------------------------------------------
// 3-phase scan (+ cursor init fused into phase C)
// ---------------------------------------------------------------------------
__global__ __launch_bounds__(1024) void scanA_kernel(int n) {
    __shared__ int warpSums[32];
    int tid  = threadIdx.x;
    int lane = tid & 31;
    int wid  = tid >> 5;
    int i = blockIdx.x * 1024 + tid;

    int v = (i < n) ? g_deg[i] : 0;
    int s = v;
#pragma unroll
    for (int off = 1; off < 32; off <<= 1) {
        int t = __shfl_up_sync(0xffffffff, s, off);
        if (lane >= off) s += t;
    }
    if (lane == 31) warpSums[wid] = s;
    __syncthreads();
    if (wid == 0) {
        int ws = warpSums[lane];
#pragma unroll
        for (int off = 1; off < 32; off <<= 1) {
            int t = __shfl_up_sync(0xffffffff, ws, off);
            if (lane >= off) ws += t;
        }
        warpSums[lane] = ws;
    }
    __syncthreads();
    int blockPrefix = (wid > 0) ? warpSums[wid - 1] : 0;
    int incl = s + blockPrefix;
    if (i < n) g_rowStart[i + 1] = incl;
    if (tid == 1023) g_blockSums[blockIdx.x] = incl;
}

__global__ __launch_bounds__(128) void scanB_kernel(int nBlocks) {
    __shared__ int sh[128];
    int tid = threadIdx.x;
    int v = (tid < nBlocks) ? g_blockSums[tid] : 0;
    sh[tid] = v;
    __syncthreads();
    for (int off = 1; off < 128; off <<= 1) {
        int t = (tid >= off) ? sh[tid - off] : 0;
        __syncthreads();
        sh[tid] += t;
        __syncthreads();
    }
    if (tid < nBlocks) g_blockSums[tid] = (tid > 0) ? sh[tid - 1] : 0;
}

__global__ __launch_bounds__(1024) void scanC_kernel(int n) {
    int i = blockIdx.x * 1024 + threadIdx.x;
    int off = g_blockSums[blockIdx.x];
    if (i < n) {
        int v = g_rowStart[i + 1] + off;
        g_rowStart[i + 1] = v;
        if (i + 1 < n) g_cursor[i + 1] = v;     // cursor[j] = rowStart[j]
    }
    if (i == 0) { g_rowStart[0] = 0; g_cursor[0] = 0; }
}

__global__ void scatter_kernel(const int* __restrict__ ei, int E) {
    int e = blockIdx.x * blockDim.x + threadIdx.x;
    if (e < E) {
        int r = ei[e];
        int c = ei[E + e];
        int pos = atomicAdd(&g_cursor[c], 1);
        g_src[pos] = r;
    }
}

// ---------------------------------------------------------------------------
// Tensor-core GEMM with bf16 split precision + register-prefetch pipeline.
//   C = A @ W (+bias),  A fp32 [M,K], W pre-split hi/lo bf16 [K,128].
//   acc += Ahi*Whi + Ahi*Wlo + Alo*Whi  (fp32 accum)
// BM=128 BN=128 BK=16; 8 warps, each 32x64 (2x4 wmma frags).
// Next tile's LDGs issue before the mma block -> overlap load with compute.
// ---------------------------------------------------------------------------
#define APITCH 24
#define BPITCH 136

__global__ __launch_bounds__(256, 2) void gemm_tc_kernel(
    const float* __restrict__ Aext, long aoff,
    long woff,
    float* __restrict__ Cext, long coff,
    const float* __restrict__ cBias,
    int M, int K)
{
    const float* A = Aext ? Aext : scr(aoff);
    float*       C = Cext ? Cext : scr(coff);

    __shared__ __align__(16) char smemRaw[32768];
    __nv_bfloat16* As_hi = reinterpret_cast<__nv_bfloat16*>(smemRaw);
    __nv_bfloat16* As_lo = reinterpret_cast<__nv_bfloat16*>(smemRaw + 6144);
    __nv_bfloat16* Bs_hi = reinterpret_cast<__nv_bfloat16*>(smemRaw + 12288);
    __nv_bfloat16* Bs_lo = reinterpret_cast<__nv_bfloat16*>(smemRaw + 16640);

    int tid  = threadIdx.x;
    int wid  = tid >> 5;
    int lane = tid & 31;
    int warp_m = wid & 3;
    int warp_n = wid >> 2;
    int m0 = blockIdx.x * 128;

    wmma::fragment<wmma::accumulator, 16, 16, 16, float> acc[2][4];
#pragma unroll
    for (int i = 0; i < 2; i++)
#pragma unroll
        for (int j = 0; j < 4; j++) wmma::fill_fragment(acc[i][j], 0.f);

    int la_m = tid >> 1;
    int la_c = (tid & 1) * 8;
    int lb_k = tid >> 4;
    int lb_n = (tid & 15) * 8;

    const __nv_bfloat16* Whi = g_whi + woff;
    const __nv_bfloat16* Wlo = g_wlo + woff;

    int gm = m0 + la_m;
    bool aValid = (gm < M);
    const float* aBase = &A[(size_t)(aValid ? gm : 0) * K + la_c];

    // ---- prefetch tile 0 into registers ----
    float va[8];
    uint4 vbh, vbl;
    {
        if (aValid) {
            float4 v0 = *reinterpret_cast<const float4*>(aBase);
            float4 v1 = *reinterpret_cast<const float4*>(aBase + 4);
            va[0]=v0.x; va[1]=v0.y; va[2]=v0.z; va[3]=v0.w;
            va[4]=v1.x; va[5]=v1.y; va[6]=v1.z; va[7]=v1.w;
        } else {
#pragma unroll
            for (int q = 0; q < 8; q++) va[q] = 0.f;
        }
        size_t gOff = (size_t)lb_k * 128 + lb_n;
        vbh = *reinterpret_cast<const uint4*>(&Whi[gOff]);
        vbl = *reinterpret_cast<const uint4*>(&Wlo[gOff]);
    }

    for (int k0 = 0; k0 < K; k0 += 16) {
        // ---- stage current tile to smem ----
        {
            __nv_bfloat16 hi[8], lo[8];
#pragma unroll
            for (int q = 0; q < 8; q++) {
                hi[q] = __float2bfloat16(va[q]);
                lo[q] = __float2bfloat16(va[q] - __bfloat162float(hi[q]));
            }
            *reinterpret_cast<uint4*>(&As_hi[la_m * APITCH + la_c]) = *reinterpret_cast<uint4*>(hi);
            *reinterpret_cast<uint4*>(&As_lo[la_m * APITCH + la_c]) = *reinterpret_cast<uint4*>(lo);
            *reinterpret_cast<uint4*>(&Bs_hi[lb_k * BPITCH + lb_n]) = vbh;
            *reinterpret_cast<uint4*>(&Bs_lo[lb_k * BPITCH + lb_n]) = vbl;
        }
        __syncthreads();

        // ---- issue next tile's LDGs (overlap with mma below) ----
        int k1 = k0 + 16;
        if (k1 < K) {
            if (aValid) {
                float4 v0 = *reinterpret_cast<const float4*>(aBase + k1);
                float4 v1 = *reinterpret_cast<const float4*>(aBase + k1 + 4);
                va[0]=v0.x; va[1]=v0.y; va[2]=v0.z; va[3]=v0.w;
                va[4]=v1.x; va[5]=v1.y; va[6]=v1.z; va[7]=v1.w;
            }
            size_t gOff = (size_t)(k1 + lb_k) * 128 + lb_n;
            vbh = *reinterpret_cast<const uint4*>(&Whi[gOff]);
            vbl = *reinterpret_cast<const uint4*>(&Wlo[gOff]);
        }

        // ---- mma ----
        wmma::fragment<wmma::matrix_b, 16, 16, 16, __nv_bfloat16, wmma::row_major> b_hi[4], b_lo[4];
#pragma unroll
        for (int j = 0; j < 4; j++) {
            wmma::load_matrix_sync(b_hi[j], &Bs_hi[warp_n * 64 + j * 16], BPITCH);
            wmma::load_matrix_sync(b_lo[j], &Bs_lo[warp_n * 64 + j * 16], BPITCH);
        }
#pragma unroll
        for (int i = 0; i < 2; i++) {
            wmma::fragment<wmma::matrix_a, 16, 16, 16, __nv_bfloat16, wmma::row_major> a_hi, a_lo;
            wmma::load_matrix_sync(a_hi, &As_hi[(warp_m * 32 + i * 16) * APITCH], APITCH);
            wmma::load_matrix_sync(a_lo, &As_lo[(warp_m * 32 + i * 16) * APITCH], APITCH);
#pragma unroll
            for (int j = 0; j < 4; j++) {
                wmma::mma_sync(acc[i][j], a_hi, b_hi[j], acc[i][j]);
                wmma::mma_sync(acc[i][j], a_hi, b_lo[j], acc[i][j]);
                wmma::mma_sync(acc[i][j], a_lo, b_hi[j], acc[i][j]);
            }
        }
        __syncthreads();
    }

    // ---- epilogue: stage 16x64 per warp through smem, fuse bias, guard M ----
    float* stage = reinterpret_cast<float*>(smemRaw) + wid * 16 * 64;
#pragma unroll
    for (int i = 0; i < 2; i++) {
#pragma unroll
        for (int j = 0; j < 4; j++)
            wmma::store_matrix_sync(&stage[j * 16], acc[i][j], 64, wmma::mem_row_major);
        __syncwarp();
#pragma unroll
        for (int p = 0; p < 8; p++) {
            int row = p * 2 + (lane >> 4);
            int gmo = m0 + warp_m * 32 + i * 16 + row;
            if (gmo < M) {
                int c4 = lane & 15;
                int gcol = warp_n * 64 + c4 * 4;
                float4 v = *reinterpret_cast<float4*>(&stage[row * 64 + c4 * 4]);
                if (cBias) {
                    float4 bb = *reinterpret_cast<const float4*>(&cBias[gcol]);
                    v.x += bb.x; v.y += bb.y; v.z += bb.z; v.w += bb.w;
                }
                *reinterpret_cast<float4*>(&C[(size_t)gmo * 128 + gcol]) = v;
            }
        }
        __syncwarp();
    }
}

// ---------------------------------------------------------------------------
// CSR aggregate: one warp per target node c; lane owns 4 features.
//   out[c] = dinv[c] * ( sum_{r in N(c)} dinv[r]*h[r] + dinv[c]*h[c] ) + b
// ---------------------------------------------------------------------------
__global__ __launch_bounds__(256) void csr_agg_kernel(
    long hoff, const float* __restrict__ bias,
    float* __restrict__ outExt, long outOff, int N)
{
    const float* h = scr(hoff);
    float* out     = outExt ? outExt : scr(outOff);

    int c = blockIdx.x * (blockDim.x >> 5) + (threadIdx.x >> 5);
    if (c >= N) return;
    int lane = threadIdx.x & 31;

    float dc = g_dinv[c];
    int start = g_rowStart[c];
    int end   = g_rowStart[c + 1];

    float4 acc = __ldg(reinterpret_cast<const float4*>(h + (size_t)c * HIDDIM) + lane);
    acc.x *= dc; acc.y *= dc; acc.z *= dc; acc.w *= dc;

    int j = start;
    for (; j + 4 <= end; j += 4) {
        int r0 = __ldg(&g_src[j + 0]);
        int r1 = __ldg(&g_src[j + 1]);
        int r2 = __ldg(&g_src[j + 2]);
        int r3 = __ldg(&g_src[j + 3]);
        float s0 = __ldg(&g_dinv[r0]);
        float s1 = __ldg(&g_dinv[r1]);
        float s2 = __ldg(&g_dinv[r2]);
        float s3 = __ldg(&g_dinv[r3]);
        float4 v0 = __ldg(reinterpret_cast<const float4*>(h + (size_t)r0 * HIDDIM) + lane);
        float4 v1 = __ldg(reinterpret_cast<const float4*>(h + (size_t)r1 * HIDDIM) + lane);
        float4 v2 = __ldg(reinterpret_cast<const float4*>(h + (size_t)r2 * HIDDIM) + lane);
        float4 v3 = __ldg(reinterpret_cast<const float4*>(h + (size_t)r3 * HIDDIM) + lane);
        acc.x += s0 * v0.x + s1 * v1.x + s2 * v2.x + s3 * v3.x;
        acc.y += s0 * v0.y + s1 * v1.y + s2 * v2.y + s3 * v3.y;
        acc.z += s0 * v0.z + s1 * v1.z + s2 * v2.z + s3 * v3.z;
        acc.w += s0 * v0.w + s1 * v1.w + s2 * v2.w + s3 * v3.w;
    }
    for (; j < end; j++) {
        int r = __ldg(&g_src[j]);
        float s = __ldg(&g_dinv[r]);
        float4 v = __ldg(reinterpret_cast<const float4*>(h + (size_t)r * HIDDIM) + lane);
        acc.x += s * v.x; acc.y += s * v.y; acc.z += s * v.z; acc.w += s * v.w;
    }

    const float4 bb = __ldg(reinterpret_cast<const float4*>(bias) + lane);
    float4 o;
    o.x = acc.x * dc + bb.x;
    o.y = acc.y * dc + bb.y;
    o.z = acc.z * dc + bb.z;
    o.w = acc.w * dc + bb.w;
    reinterpret_cast<float4*>(out + (size_t)c * HIDDIM)[lane] = o;
}

// ---------------------------------------------------------------------------
// launch — kernels only, no runtime API calls
// ---------------------------------------------------------------------------
extern "C" void kernel_launch(void* const* d_in, const int* in_sizes, int n_in,
                              void* d_out, int out_size)
{
    const float* x  = (const float*)d_in[0];
    const int*   ei = (const int*)d_in[1];       // int32 edge index
    const float* W1 = (const float*)d_in[2];
    const float* b1 = (const float*)d_in[3];
    const float* W2 = (const float*)d_in[4];
    const float* b2 = (const float*)d_in[5];
    const float* Wp = (const float*)d_in[6];
    const float* bp = (const float*)d_in[7];

    int N = in_sizes[0] / INDIM;          // 100000
    int E = in_sizes[1] / 2;              // 1600000

    float* z    = (float*)d_out;                       // z2 [N,128]
    float* proj = z + (size_t)N * HIDDIM;              // projection

    const int T = 256;
    int nBlocksN    = (N + T - 1) / T;
    int nBlocksE    = (E + T - 1) / T;
    int nBlocksGemm = (N + 127) / 128;
    int nBlocksWarp = (N + 7) / 8;
    int nScanBlocks = (N + 1023) / 1024;

    // ---- preprocessing: degrees, dinv, CSR by target, weight splits ----
    zero_deg_kernel<<<nBlocksN, T>>>(N);
    count_deg_kernel<<<nBlocksE, T>>>(ei, E);
    dinv_kernel<<<nBlocksN, T>>>(N);
    scanA_kernel<<<nScanBlocks, 1024>>>(N);
    scanB_kernel<<<1, 128>>>(nScanBlocks);
    scanC_kernel<<<nScanBlocks, 1024>>>(N);
    scatter_kernel<<<nBlocksE, T>>>(ei, E);
    convert_w_kernel<<<65536 / T, T>>>(W1, W2, Wp);

    // layer 1: h1 = x @ W1 ; z1 = csr_agg(h1) + b1
    gemm_tc_kernel<<<nBlocksGemm, T>>>(x, 0, WOFF_W1, nullptr, OFF_H1, nullptr, N, INDIM);
    csr_agg_kernel<<<nBlocksWarp, T>>>(OFF_H1, b1, nullptr, OFF_Z1, N);

    // layer 2: h2 = z1 @ W2 ; z = csr_agg(h2) + b2  (into d_out)
    gemm_tc_kernel<<<nBlocksGemm, T>>>(nullptr, OFF_Z1, WOFF_W2, nullptr, OFF_H2, nullptr, N, HIDDIM);
    csr_agg_kernel<<<nBlocksWarp, T>>>(OFF_H2, b2, z, 0, N);

    // projection head: proj = z @ Wp + bp
    gemm_tc_kernel<<<nBlocksGemm, T>>>(z, 0, WOFF_WP, proj, 0, bp, N, HIDDIM);
}

// round 15
// speedup vs baseline: 1.0234x; 1.0234x over previous
#include <cuda_runtime.h>
#include <cuda_bf16.h>
#include <mma.h>
#include <cstdint>

using namespace nvcuda;

#define NNODES 100000
#define HIDDIM 128
#define INDIM  256
#define MAXE   1600000
#define NF ((long)NNODES * HIDDIM)        // 12,800,000 floats per buffer

// Scratch (static device globals — no allocation allowed)
__device__ float4 g_scratch[3 * NF / 4];  // h1, z1, h2
__device__ int    g_deg[NNODES];
__device__ float  g_dinv[NNODES];
__device__ int    g_rowStart[NNODES + 1]; // CSR offsets (by target node)
__device__ int    g_cursor[NNODES];
__device__ int    g_src[MAXE];            // source node per CSR slot
__device__ int    g_blockSums[256];
// split-precision weights: W1(32768) | W2(16384) | Wp(16384)
__device__ __nv_bfloat16 g_whi[65536];
__device__ __nv_bfloat16 g_wlo[65536];

__device__ __forceinline__ float* scr(long off) {
    return reinterpret_cast<float*>(g_scratch) + off;
}

#define OFF_H1 ((long)0)
#define OFF_Z1 (NF)
#define OFF_H2 (2 * NF)
#define WOFF_W1 0
#define WOFF_W2 32768
#define WOFF_WP 49152

// ---------------------------------------------------------------------------
// degree / norm
// ---------------------------------------------------------------------------
__global__ void zero_deg_kernel(int n) {
    int i = blockIdx.x * blockDim.x + threadIdx.x;
    if (i < n) g_deg[i] = 0;
}

__global__ void count_deg_kernel(const int* __restrict__ ei, int E) {
    int e = blockIdx.x * blockDim.x + threadIdx.x;
    if (e < E) atomicAdd(&g_deg[ei[E + e]], 1);
}

__global__ void dinv_kernel(int n) {
    int i = blockIdx.x * blockDim.x + threadIdx.x;
    if (i < n) g_dinv[i] = rsqrtf((float)(g_deg[i] + 1));
}

// ---------------------------------------------------------------------------
// weight split: all three W -> hi + lo bf16 in one launch
// ---------------------------------------------------------------------------
__global__ void convert_w_kernel(const float* __restrict__ W1,
                                 const float* __restrict__ W2,
                                 const float* __restrict__ Wp) {
    int i = blockIdx.x * blockDim.x + threadIdx.x;   // 0..65535
    float v;
    if (i < 32768)       v = W1[i];
    else if (i < 49152)  v = W2[i - 32768];
    else                 v = Wp[i - 49152];
    __nv_bfloat16 hi = __float2bfloat16(v);
    __nv_bfloat16 lo = __float2bfloat16(v - __bfloat162float(hi));
    g_whi[i] = hi;
    g_wlo[i] = lo;
}

// ---------------------------------------------------------------------------
// 3-phase scan (+ cursor init fused into phase C)
// ---------------------------------------------------------------------------
__global__ __launch_bounds__(1024) void scanA_kernel(int n) {
    __shared__ int warpSums[32];
    int tid  = threadIdx.x;
    int lane = tid & 31;
    int wid  = tid >> 5;
    int i = blockIdx.x * 1024 + tid;

    int v = (i < n) ? g_deg[i] : 0;
    int s = v;
#pragma unroll
    for (int off = 1; off < 32; off <<= 1) {
        int t = __shfl_up_sync(0xffffffff, s, off);
        if (lane >= off) s += t;
    }
    if (lane == 31) warpSums[wid] = s;
    __syncthreads();
    if (wid == 0) {
        int ws = warpSums[lane];
#pragma unroll
        for (int off = 1; off < 32; off <<= 1) {
            int t = __shfl_up_sync(0xffffffff, ws, off);
            if (lane >= off) ws += t;
        }
        warpSums[lane] = ws;
    }
    __syncthreads();
    int blockPrefix = (wid > 0) ? warpSums[wid - 1] : 0;
    int incl = s + blockPrefix;
    if (i < n) g_rowStart[i + 1] = incl;
    if (tid == 1023) g_blockSums[blockIdx.x] = incl;
}

__global__ __launch_bounds__(128) void scanB_kernel(int nBlocks) {
    __shared__ int sh[128];
    int tid = threadIdx.x;
    int v = (tid < nBlocks) ? g_blockSums[tid] : 0;
    sh[tid] = v;
    __syncthreads();
    for (int off = 1; off < 128; off <<= 1) {
        int t = (tid >= off) ? sh[tid - off] : 0;
        __syncthreads();
        sh[tid] += t;
        __syncthreads();
    }
    if (tid < nBlocks) g_blockSums[tid] = (tid > 0) ? sh[tid - 1] : 0;
}

__global__ __launch_bounds__(1024) void scanC_kernel(int n) {
    int i = blockIdx.x * 1024 + threadIdx.x;
    int off = g_blockSums[blockIdx.x];
    if (i < n) {
        int v = g_rowStart[i + 1] + off;
        g_rowStart[i + 1] = v;
        if (i + 1 < n) g_cursor[i + 1] = v;     // cursor[j] = rowStart[j]
    }
    if (i == 0) { g_rowStart[0] = 0; g_cursor[0] = 0; }
}

__global__ void scatter_kernel(const int* __restrict__ ei, int E) {
    int e = blockIdx.x * blockDim.x + threadIdx.x;
    if (e < E) {
        int r = ei[e];
        int c = ei[E + e];
        int pos = atomicAdd(&g_cursor[c], 1);
        g_src[pos] = r;
    }
}

// ---------------------------------------------------------------------------
// Tensor-core GEMM, bf16 split precision, DOUBLE-BUFFERED smem pipeline.
//   C = A @ W (+bias),  A fp32 [M,K], W pre-split hi/lo bf16 [K,128].
//   acc += Ahi*Whi + Ahi*Wlo + Alo*Whi  (fp32 accum)
// BM=128 BN=128 BK=16; 8 warps x (32x64). One __syncthreads per K-tile;
// next tile's LDGs issue before the mma block; b-frags transient (low regs).
// ---------------------------------------------------------------------------
#define APITCH 24
#define BPITCH 136
#define BUFBYTES 20992      // As_hi(6144)+As_lo(6144)+Bs_hi(4352)+Bs_lo(4352)

__global__ __launch_bounds__(256, 2) void gemm_tc_kernel(
    const float* __restrict__ Aext, long aoff,
    long woff,
    float* __restrict__ Cext, long coff,
    const float* __restrict__ cBias,
    int M, int K)
{
    const float* A = Aext ? Aext : scr(aoff);
    float*       C = Cext ? Cext : scr(coff);

    __shared__ __align__(16) char smemRaw[2 * BUFBYTES];   // 41984 B

    int tid  = threadIdx.x;
    int wid  = tid >> 5;
    int lane = tid & 31;
    int warp_m = wid & 3;
    int warp_n = wid >> 2;
    int m0 = blockIdx.x * 128;

    wmma::fragment<wmma::accumulator, 16, 16, 16, float> acc[2][4];
#pragma unroll
    for (int i = 0; i < 2; i++)
#pragma unroll
        for (int j = 0; j < 4; j++) wmma::fill_fragment(acc[i][j], 0.f);

    int la_m = tid >> 1;
    int la_c = (tid & 1) * 8;
    int lb_k = tid >> 4;
    int lb_n = (tid & 15) * 8;

    const __nv_bfloat16* Whi = g_whi + woff;
    const __nv_bfloat16* Wlo = g_wlo + woff;

    int gm = m0 + la_m;
    bool aValid = (gm < M);
    const float* aBase = &A[(size_t)(aValid ? gm : 0) * K + la_c];

    // ---- prologue: tile 0 -> buffer 0 ----
    {
        char* buf = smemRaw;
        __nv_bfloat16* As_hi = reinterpret_cast<__nv_bfloat16*>(buf);
        __nv_bfloat16* As_lo = reinterpret_cast<__nv_bfloat16*>(buf + 6144);
        __nv_bfloat16* Bs_hi = reinterpret_cast<__nv_bfloat16*>(buf + 12288);
        __nv_bfloat16* Bs_lo = reinterpret_cast<__nv_bfloat16*>(buf + 16640);

        float va[8];
        if (aValid) {
            float4 v0 = *reinterpret_cast<const float4*>(aBase);
            float4 v1 = *reinterpret_cast<const float4*>(aBase + 4);
            va[0]=v0.x; va[1]=v0.y; va[2]=v0.z; va[3]=v0.w;
            va[4]=v1.x; va[5]=v1.y; va[6]=v1.z; va[7]=v1.w;
        } else {
#pragma unroll
            for (int q = 0; q < 8; q++) va[q] = 0.f;
        }
        __nv_bfloat16 hi[8], lo[8];
#pragma unroll
        for (int q = 0; q < 8; q++) {
            hi[q] = __float2bfloat16(va[q]);
            lo[q] = __float2bfloat16(va[q] - __bfloat162float(hi[q]));
        }
        *reinterpret_cast<uint4*>(&As_hi[la_m * APITCH + la_c]) = *reinterpret_cast<uint4*>(hi);
        *reinterpret_cast<uint4*>(&As_lo[la_m * APITCH + la_c]) = *reinterpret_cast<uint4*>(lo);
        size_t gOff = (size_t)lb_k * 128 + lb_n;
        *reinterpret_cast<uint4*>(&Bs_hi[lb_k * BPITCH + lb_n]) =
            *reinterpret_cast<const uint4*>(&Whi[gOff]);
        *reinterpret_cast<uint4*>(&Bs_lo[lb_k * BPITCH + lb_n]) =
            *reinterpret_cast<const uint4*>(&Wlo[gOff]);
    }
    __syncthreads();

    for (int k0 = 0, cur = 0; k0 < K; k0 += 16, cur ^= 1) {
        char* bufC = smemRaw + cur * BUFBYTES;
        char* bufN = smemRaw + (cur ^ 1) * BUFBYTES;
        __nv_bfloat16* As_hi = reinterpret_cast<__nv_bfloat16*>(bufC);
        __nv_bfloat16* As_lo = reinterpret_cast<__nv_bfloat16*>(bufC + 6144);
        __nv_bfloat16* Bs_hi = reinterpret_cast<__nv_bfloat16*>(bufC + 12288);
        __nv_bfloat16* Bs_lo = reinterpret_cast<__nv_bfloat16*>(bufC + 16640);

        // ---- issue next tile's LDGs (consumed after the mma block) ----
        int k1 = k0 + 16;
        bool hasNext = (k1 < K);
        float va[8];
        uint4 vbh, vbl;
        if (hasNext) {
            if (aValid) {
                float4 v0 = *reinterpret_cast<const float4*>(aBase + k1);
                float4 v1 = *reinterpret_cast<const float4*>(aBase + k1 + 4);
                va[0]=v0.x; va[1]=v0.y; va[2]=v0.z; va[3]=v0.w;
                va[4]=v1.x; va[5]=v1.y; va[6]=v1.z; va[7]=v1.w;
            } else {
#pragma unroll
                for (int q = 0; q < 8; q++) va[q] = 0.f;
            }
            size_t gOff = (size_t)(k1 + lb_k) * 128 + lb_n;
            vbh = *reinterpret_cast<const uint4*>(&Whi[gOff]);
            vbl = *reinterpret_cast<const uint4*>(&Wlo[gOff]);
        }

        // ---- mma on current buffer (i outer, b-frags transient) ----
#pragma unroll
        for (int i = 0; i < 2; i++) {
            wmma::fragment<wmma::matrix_a, 16, 16, 16, __nv_bfloat16, wmma::row_major> a_hi, a_lo;
            wmma::load_matrix_sync(a_hi, &As_hi[(warp_m * 32 + i * 16) * APITCH], APITCH);
            wmma::load_matrix_sync(a_lo, &As_lo[(warp_m * 32 + i * 16) * APITCH], APITCH);
#pragma unroll
            for (int j = 0; j < 4; j++) {
                wmma::fragment<wmma::matrix_b, 16, 16, 16, __nv_bfloat16, wmma::row_major> b_hi, b_lo;
                wmma::load_matrix_sync(b_hi, &Bs_hi[warp_n * 64 + j * 16], BPITCH);
                wmma::load_matrix_sync(b_lo, &Bs_lo[warp_n * 64 + j * 16], BPITCH);
                wmma::mma_sync(acc[i][j], a_hi, b_hi, acc[i][j]);
                wmma::mma_sync(acc[i][j], a_hi, b_lo, acc[i][j]);
                wmma::mma_sync(acc[i][j], a_lo, b_hi, acc[i][j]);
            }
        }

        // ---- stage next tile into alternate buffer ----
        if (hasNext) {
            __nv_bfloat16* nAs_hi = reinterpret_cast<__nv_bfloat16*>(bufN);
            __nv_bfloat16* nAs_lo = reinterpret_cast<__nv_bfloat16*>(bufN + 6144);
            __nv_bfloat16* nBs_hi = reinterpret_cast<__nv_bfloat16*>(bufN + 12288);
            __nv_bfloat16* nBs_lo = reinterpret_cast<__nv_bfloat16*>(bufN + 16640);
            __nv_bfloat16 hi[8], lo[8];
#pragma unroll
            for (int q = 0; q < 8; q++) {
                hi[q] = __float2bfloat16(va[q]);
                lo[q] = __float2bfloat16(va[q] - __bfloat162float(hi[q]));
            }
            *reinterpret_cast<uint4*>(&nAs_hi[la_m * APITCH + la_c]) = *reinterpret_cast<uint4*>(hi);
            *reinterpret_cast<uint4*>(&nAs_lo[la_m * APITCH + la_c]) = *reinterpret_cast<uint4*>(lo);
            *reinterpret_cast<uint4*>(&nBs_hi[lb_k * BPITCH + lb_n]) = vbh;
            *reinterpret_cast<uint4*>(&nBs_lo[lb_k * BPITCH + lb_n]) = vbl;
        }
        __syncthreads();
    }

    // ---- epilogue: stage 16x64 per warp through smem, fuse bias, guard M ----
    float* stage = reinterpret_cast<float*>(smemRaw) + wid * 16 * 64;
#pragma unroll
    for (int i = 0; i < 2; i++) {
#pragma unroll
        for (int j = 0; j < 4; j++)
            wmma::store_matrix_sync(&stage[j * 16], acc[i][j], 64, wmma::mem_row_major);
        __syncwarp();
#pragma unroll
        for (int p = 0; p < 8; p++) {
            int row = p * 2 + (lane >> 4);
            int gmo = m0 + warp_m * 32 + i * 16 + row;
            if (gmo < M) {
                int c4 = lane & 15;
                int gcol = warp_n * 64 + c4 * 4;
                float4 v = *reinterpret_cast<float4*>(&stage[row * 64 + c4 * 4]);
                if (cBias) {
                    float4 bb = *reinterpret_cast<const float4*>(&cBias[gcol]);
                    v.x += bb.x; v.y += bb.y; v.z += bb.z; v.w += bb.w;
                }
                *reinterpret_cast<float4*>(&C[(size_t)gmo * 128 + gcol]) = v;
            }
        }
        __syncwarp();
    }
}

// ---------------------------------------------------------------------------
// CSR aggregate: one warp per target node c; lane owns 4 features.
//   out[c] = dinv[c] * ( sum_{r in N(c)} dinv[r]*h[r] + dinv[c]*h[c] ) + b
// ---------------------------------------------------------------------------
__global__ __launch_bounds__(256) void csr_agg_kernel(
    long hoff, const float* __restrict__ bias,
    float* __restrict__ outExt, long outOff, int N)
{
    const float* h = scr(hoff);
    float* out     = outExt ? outExt : scr(outOff);

    int c = blockIdx.x * (blockDim.x >> 5) + (threadIdx.x >> 5);
    if (c >= N) return;
    int lane = threadIdx.x & 31;

    float dc = g_dinv[c];
    int start = g_rowStart[c];
    int end   = g_rowStart[c + 1];

    float4 acc = __ldg(reinterpret_cast<const float4*>(h + (size_t)c * HIDDIM) + lane);
    acc.x *= dc; acc.y *= dc; acc.z *= dc; acc.w *= dc;

    int j = start;
    for (; j + 4 <= end; j += 4) {
        int r0 = __ldg(&g_src[j + 0]);
        int r1 = __ldg(&g_src[j + 1]);
        int r2 = __ldg(&g_src[j + 2]);
        int r3 = __ldg(&g_src[j + 3]);
        float s0 = __ldg(&g_dinv[r0]);
        float s1 = __ldg(&g_dinv[r1]);
        float s2 = __ldg(&g_dinv[r2]);
        float s3 = __ldg(&g_dinv[r3]);
        float4 v0 = __ldg(reinterpret_cast<const float4*>(h + (size_t)r0 * HIDDIM) + lane);
        float4 v1 = __ldg(reinterpret_cast<const float4*>(h + (size_t)r1 * HIDDIM) + lane);
        float4 v2 = __ldg(reinterpret_cast<const float4*>(h + (size_t)r2 * HIDDIM) + lane);
        float4 v3 = __ldg(reinterpret_cast<const float4*>(h + (size_t)r3 * HIDDIM) + lane);
        acc.x += s0 * v0.x + s1 * v1.x + s2 * v2.x + s3 * v3.x;
        acc.y += s0 * v0.y + s1 * v1.y + s2 * v2.y + s3 * v3.y;
        acc.z += s0 * v0.z + s1 * v1.z + s2 * v2.z + s3 * v3.z;
        acc.w += s0 * v0.w + s1 * v1.w + s2 * v2.w + s3 * v3.w;
    }
    for (; j < end; j++) {
        int r = __ldg(&g_src[j]);
        float s = __ldg(&g_dinv[r]);
        float4 v = __ldg(reinterpret_cast<const float4*>(h + (size_t)r * HIDDIM) + lane);
        acc.x += s * v.x; acc.y += s * v.y; acc.z += s * v.z; acc.w += s * v.w;
    }

    const float4 bb = __ldg(reinterpret_cast<const float4*>(bias) + lane);
    float4 o;
    o.x = acc.x * dc + bb.x;
    o.y = acc.y * dc + bb.y;
    o.z = acc.z * dc + bb.z;
    o.w = acc.w * dc + bb.w;
    reinterpret_cast<float4*>(out + (size_t)c * HIDDIM)[lane] = o;
}

// ---------------------------------------------------------------------------
// launch — kernels only, no runtime API calls
// ---------------------------------------------------------------------------
extern "C" void kernel_launch(void* const* d_in, const int* in_sizes, int n_in,
                              void* d_out, int out_size)
{
    const float* x  = (const float*)d_in[0];
    const int*   ei = (const int*)d_in[1];       // int32 edge index
    const float* W1 = (const float*)d_in[2];
    const float* b1 = (const float*)d_in[3];
    const float* W2 = (const float*)d_in[4];
    const float* b2 = (const float*)d_in[5];
    const float* Wp = (const float*)d_in[6];
    const float* bp = (const float*)d_in[7];

    int N = in_sizes[0] / INDIM;          // 100000
    int E = in_sizes[1] / 2;              // 1600000

    float* z    = (float*)d_out;                       // z2 [N,128]
    float* proj = z + (size_t)N * HIDDIM;              // projection

    const int T = 256;
    int nBlocksN    = (N + T - 1) / T;
    int nBlocksE    = (E + T - 1) / T;
    int nBlocksGemm = (N + 127) / 128;
    int nBlocksWarp = (N + 7) / 8;
    int nScanBlocks = (N + 1023) / 1024;

    // ---- preprocessing: degrees, dinv, CSR by target, weight splits ----
    zero_deg_kernel<<<nBlocksN, T>>>(N);
    count_deg_kernel<<<nBlocksE, T>>>(ei, E);
    dinv_kernel<<<nBlocksN, T>>>(N);
    scanA_kernel<<<nScanBlocks, 1024>>>(N);
    scanB_kernel<<<1, 128>>>(nScanBlocks);
    scanC_kernel<<<nScanBlocks, 1024>>>(N);
    scatter_kernel<<<nBlocksE, T>>>(ei, E);
    convert_w_kernel<<<65536 / T, T>>>(W1, W2, Wp);

    // layer 1: h1 = x @ W1 ; z1 = csr_agg(h1) + b1
    gemm_tc_kernel<<<nBlocksGemm, T>>>(x, 0, WOFF_W1, nullptr, OFF_H1, nullptr, N, INDIM);
    csr_agg_kernel<<<nBlocksWarp, T>>>(OFF_H1, b1, nullptr, OFF_Z1, N);

    // layer 2: h2 = z1 @ W2 ; z = csr_agg(h2) + b2  (into d_out)
    gemm_tc_kernel<<<nBlocksGemm, T>>>(nullptr, OFF_Z1, WOFF_W2, nullptr, OFF_H2, nullptr, N, HIDDIM);
    csr_agg_kernel<<<nBlocksWarp, T>>>(OFF_H2, b2, z, 0, N);

    // projection head: proj = z @ Wp + bp
    gemm_tc_kernel<<<nBlocksGemm, T>>>(z, 0, WOFF_WP, proj, 0, bp, N, HIDDIM);
}

// round 17
// speedup vs baseline: 1.0957x; 1.0707x over previous
#include <cuda_runtime.h>
#include <cuda_bf16.h>
#include <cuda_fp16.h>
#include <mma.h>
#include <cstdint>

using namespace nvcuda;

#define NNODES 100000
#define HIDDIM 128
#define INDIM  256
#define MAXE   1600000
#define NF ((long)NNODES * HIDDIM)        // 12,800,000 elems per buffer

// Scratch (static device globals — no allocation allowed)
__device__ float4 g_scratch[NF / 4];      // z1 (fp32)
__device__ uint2  g_h[NF / 4];            // h buffer, fp16 x4 per uint2 (shared by both layers)
__device__ int    g_deg[NNODES];
__device__ float  g_dinv[NNODES];
__device__ int    g_rowStart[NNODES + 1]; // CSR offsets (by target node)
__device__ int    g_cursor[NNODES];
__device__ int    g_src[MAXE];            // source node per CSR slot
__device__ int    g_blockSums[256];
// split-precision weights: W1(32768) | W2(16384) | Wp(16384)
__device__ __nv_bfloat16 g_whi[65536];
__device__ __nv_bfloat16 g_wlo[65536];

__device__ __forceinline__ float* scr(long off) {
    return reinterpret_cast<float*>(g_scratch) + off;
}

#define OFF_Z1 ((long)0)
#define WOFF_W1 0
#define WOFF_W2 32768
#define WOFF_WP 49152

// ---------------------------------------------------------------------------
// degree / norm
// ---------------------------------------------------------------------------
__global__ void zero_deg_kernel(int n) {
    int i = blockIdx.x * blockDim.x + threadIdx.x;
    if (i < n) g_deg[i] = 0;
}

__global__ void count_deg_kernel(const int* __restrict__ ei, int E) {
    int e = blockIdx.x * blockDim.x + threadIdx.x;
    if (e < E) atomicAdd(&g_deg[ei[E + e]], 1);
}

__global__ void dinv_kernel(int n) {
    int i = blockIdx.x * blockDim.x + threadIdx.x;
    if (i < n) g_dinv[i] = rsqrtf((float)(g_deg[i] + 1));
}

// ---------------------------------------------------------------------------
// weight split: all three W -> hi + lo bf16 in one launch
// ---------------------------------------------------------------------------
__global__ void convert_w_kernel(const float* __restrict__ W1,
                                 const float* __restrict__ W2,
                                 const float* __restrict__ Wp) {
    int i = blockIdx.x * blockDim.x + threadIdx.x;   // 0..65535
    float v;
    if (i < 32768)       v = W1[i];
    else if (i < 49152)  v = W2[i - 32768];
    else                 v = Wp[i - 49152];
    __nv_bfloat16 hi = __float2bfloat16(v);
    __nv_bfloat16 lo = __float2bfloat16(v - __bfloat162float(hi));
    g_whi[i] = hi;
    g_wlo[i] = lo;
}

// ---------------------------------------------------------------------------
// 3-phase scan (+ cursor init fused into phase C)
// ---------------------------------------------------------------------------
__global__ __launch_bounds__(1024) void scanA_kernel(int n) {
    __shared__ int warpSums[32];
    int tid  = threadIdx.x;
    int lane = tid & 31;
    int wid  = tid >> 5;
    int i = blockIdx.x * 1024 + tid;

    int v = (i < n) ? g_deg[i] : 0;
    int s = v;
#pragma unroll
    for (int off = 1; off < 32; off <<= 1) {
        int t = __shfl_up_sync(0xffffffff, s, off);
        if (lane >= off) s += t;
    }
    if (lane == 31) warpSums[wid] = s;
    __syncthreads();
    if (wid == 0) {
        int ws = warpSums[lane];
#pragma unroll
        for (int off = 1; off < 32; off <<= 1) {
            int t = __shfl_up_sync(0xffffffff, ws, off);
            if (lane >= off) ws += t;
        }
        warpSums[lane] = ws;
    }
    __syncthreads();
    int blockPrefix = (wid > 0) ? warpSums[wid - 1] : 0;
    int incl = s + blockPrefix;
    if (i < n) g_rowStart[i + 1] = incl;
    if (tid == 1023) g_blockSums[blockIdx.x] = incl;
}

__global__ __launch_bounds__(128) void scanB_kernel(int nBlocks) {
    __shared__ int sh[128];
    int tid = threadIdx.x;
    int v = (tid < nBlocks) ? g_blockSums[tid] : 0;
    sh[tid] = v;
    __syncthreads();
    for (int off = 1; off < 128; off <<= 1) {
        int t = (tid >= off) ? sh[tid - off] : 0;
        __syncthreads();
        sh[tid] += t;
        __syncthreads();
    }
    if (tid < nBlocks) g_blockSums[tid] = (tid > 0) ? sh[tid - 1] : 0;
}

__global__ __launch_bounds__(1024) void scanC_kernel(int n) {
    int i = blockIdx.x * 1024 + threadIdx.x;
    int off = g_blockSums[blockIdx.x];
    if (i < n) {
        int v = g_rowStart[i + 1] + off;
        g_rowStart[i + 1] = v;
        if (i + 1 < n) g_cursor[i + 1] = v;     // cursor[j] = rowStart[j]
    }
    if (i == 0) { g_rowStart[0] = 0; g_cursor[0] = 0; }
}

__global__ void scatter_kernel(const int* __restrict__ ei, int E) {
    int e = blockIdx.x * blockDim.x + threadIdx.x;
    if (e < E) {
        int r = ei[e];
        int c = ei[E + e];
        int pos = atomicAdd(&g_cursor[c], 1);
        g_src[pos] = r;
    }
}

// ---------------------------------------------------------------------------
// Tensor-core GEMM with bf16 split precision (R9 structure — proven fastest).
//   C = A @ W (+bias),  A fp32 [M,K], W pre-split hi/lo bf16 [K,128].
//   acc += Ahi*Whi + Ahi*Wlo + Alo*Whi  (fp32 accum)
// BM=128 BN=128 BK=16; 8 warps, each 32x64 (2x4 wmma frags).
// outHalf: epilogue converts to fp16 and writes g_h (for the aggregation).
// ---------------------------------------------------------------------------
#define APITCH 24
#define BPITCH 136

__global__ __launch_bounds__(256, 2) void gemm_tc_kernel(
    const float* __restrict__ Aext, long aoff,
    long woff,
    float* __restrict__ Cext, long coff,
    const float* __restrict__ cBias,
    int outHalf,
    int M, int K)
{
    const float* A = Aext ? Aext : scr(aoff);
    float*       C = Cext ? Cext : scr(coff);

    __shared__ __align__(16) char smemRaw[32768];
    __nv_bfloat16* As_hi = reinterpret_cast<__nv_bfloat16*>(smemRaw);
    __nv_bfloat16* As_lo = reinterpret_cast<__nv_bfloat16*>(smemRaw + 6144);
    __nv_bfloat16* Bs_hi = reinterpret_cast<__nv_bfloat16*>(smemRaw + 12288);
    __nv_bfloat16* Bs_lo = reinterpret_cast<__nv_bfloat16*>(smemRaw + 16640);

    int tid  = threadIdx.x;
    int wid  = tid >> 5;
    int lane = tid & 31;
    int warp_m = wid & 3;
    int warp_n = wid >> 2;
    int m0 = blockIdx.x * 128;

    wmma::fragment<wmma::accumulator, 16, 16, 16, float> acc[2][4];
#pragma unroll
    for (int i = 0; i < 2; i++)
#pragma unroll
        for (int j = 0; j < 4; j++) wmma::fill_fragment(acc[i][j], 0.f);

    int la_m = tid >> 1;
    int la_c = (tid & 1) * 8;
    int lb_k = tid >> 4;
    int lb_n = (tid & 15) * 8;

    const __nv_bfloat16* Whi = g_whi + woff;
    const __nv_bfloat16* Wlo = g_wlo + woff;

    for (int k0 = 0; k0 < K; k0 += 16) {
        // ---- load A tile [128x16] fp32 -> split bf16 smem ----
        {
            int gm = m0 + la_m;
            float v[8];
            if (gm < M) {
                const float* ap = &A[(size_t)gm * K + k0 + la_c];
                float4 v0 = *reinterpret_cast<const float4*>(ap);
                float4 v1 = *reinterpret_cast<const float4*>(ap + 4);
                v[0]=v0.x; v[1]=v0.y; v[2]=v0.z; v[3]=v0.w;
                v[4]=v1.x; v[5]=v1.y; v[6]=v1.z; v[7]=v1.w;
            } else {
#pragma unroll
                for (int q = 0; q < 8; q++) v[q] = 0.f;
            }
            __nv_bfloat16 hi[8], lo[8];
#pragma unroll
            for (int q = 0; q < 8; q++) {
                hi[q] = __float2bfloat16(v[q]);
                lo[q] = __float2bfloat16(v[q] - __bfloat162float(hi[q]));
            }
            *reinterpret_cast<uint4*>(&As_hi[la_m * APITCH + la_c]) = *reinterpret_cast<uint4*>(hi);
            *reinterpret_cast<uint4*>(&As_lo[la_m * APITCH + la_c]) = *reinterpret_cast<uint4*>(lo);
        }
        // ---- load B tile [16x128] bf16 hi/lo ----
        {
            size_t gOff = (size_t)(k0 + lb_k) * 128 + lb_n;
            *reinterpret_cast<uint4*>(&Bs_hi[lb_k * BPITCH + lb_n]) =
                *reinterpret_cast<const uint4*>(&Whi[gOff]);
            *reinterpret_cast<uint4*>(&Bs_lo[lb_k * BPITCH + lb_n]) =
                *reinterpret_cast<const uint4*>(&Wlo[gOff]);
        }
        __syncthreads();

        // ---- mma ----
        wmma::fragment<wmma::matrix_b, 16, 16, 16, __nv_bfloat16, wmma::row_major> b_hi[4], b_lo[4];
#pragma unroll
        for (int j = 0; j < 4; j++) {
            wmma::load_matrix_sync(b_hi[j], &Bs_hi[warp_n * 64 + j * 16], BPITCH);
            wmma::load_matrix_sync(b_lo[j], &Bs_lo[warp_n * 64 + j * 16], BPITCH);
        }
#pragma unroll
        for (int i = 0; i < 2; i++) {
            wmma::fragment<wmma::matrix_a, 16, 16, 16, __nv_bfloat16, wmma::row_major> a_hi, a_lo;
            wmma::load_matrix_sync(a_hi, &As_hi[(warp_m * 32 + i * 16) * APITCH], APITCH);
            wmma::load_matrix_sync(a_lo, &As_lo[(warp_m * 32 + i * 16) * APITCH], APITCH);
#pragma unroll
            for (int j = 0; j < 4; j++) {
                wmma::mma_sync(acc[i][j], a_hi, b_hi[j], acc[i][j]);
                wmma::mma_sync(acc[i][j], a_hi, b_lo[j], acc[i][j]);
                wmma::mma_sync(acc[i][j], a_lo, b_hi[j], acc[i][j]);
            }
        }
        __syncthreads();
    }

    // ---- epilogue: stage 16x64 per warp through smem, fuse bias, guard M ----
    float* stage = reinterpret_cast<float*>(smemRaw) + wid * 16 * 64;
#pragma unroll
    for (int i = 0; i < 2; i++) {
#pragma unroll
        for (int j = 0; j < 4; j++)
            wmma::store_matrix_sync(&stage[j * 16], acc[i][j], 64, wmma::mem_row_major);
        __syncwarp();
#pragma unroll
        for (int p = 0; p < 8; p++) {
            int row = p * 2 + (lane >> 4);
            int gmo = m0 + warp_m * 32 + i * 16 + row;
            if (gmo < M) {
                int c4 = lane & 15;
                int gcol = warp_n * 64 + c4 * 4;
                float4 v = *reinterpret_cast<float4*>(&stage[row * 64 + c4 * 4]);
                if (outHalf) {
                    __half h4[4];
                    h4[0] = __float2half(v.x);
                    h4[1] = __float2half(v.y);
                    h4[2] = __float2half(v.z);
                    h4[3] = __float2half(v.w);
                    g_h[(size_t)gmo * 32 + (gcol >> 2)] = *reinterpret_cast<uint2*>(h4);
                } else {
                    if (cBias) {
                        float4 bb = *reinterpret_cast<const float4*>(&cBias[gcol]);
                        v.x += bb.x; v.y += bb.y; v.z += bb.z; v.w += bb.w;
                    }
                    *reinterpret_cast<float4*>(&C[(size_t)gmo * 128 + gcol]) = v;
                }
            }
        }
        __syncwarp();
    }
}

// ---------------------------------------------------------------------------
// CSR aggregate (fp16 gather): one warp per target node c; lane owns 4 feats.
//   out[c] = dinv[c] * ( sum_{r in N(c)} dinv[r]*h[r] + dinv[c]*h[c] ) + b
// h stored fp16 (g_h); 256B gathered per edge instead of 512B. fp32 accum.
// ---------------------------------------------------------------------------
__device__ __forceinline__ float4 ldh4(uint2 u) {
    __half2 a = *reinterpret_cast<__half2*>(&u.x);
    __half2 b = *reinterpret_cast<__half2*>(&u.y);
    float2 fa = __half22float2(a);
    float2 fb = __half22float2(b);
    return make_float4(fa.x, fa.y, fb.x, fb.y);
}

__global__ __launch_bounds__(256) void csr_agg_kernel(
    const float* __restrict__ bias,
    float* __restrict__ outExt, long outOff, int N)
{
    float* out = outExt ? outExt : scr(outOff);

    int c = blockIdx.x * (blockDim.x >> 5) + (threadIdx.x >> 5);
    if (c >= N) return;
    int lane = threadIdx.x & 31;

    float dc = g_dinv[c];
    int start = g_rowStart[c];
    int end   = g_rowStart[c + 1];

    // self loop
    float4 acc = ldh4(__ldg(&g_h[(size_t)c * 32 + lane]));
    acc.x *= dc; acc.y *= dc; acc.z *= dc; acc.w *= dc;

    int j = start;
    for (; j + 4 <= end; j += 4) {
        int r0 = __ldg(&g_src[j + 0]);
        int r1 = __ldg(&g_src[j + 1]);
        int r2 = __ldg(&g_src[j + 2]);
        int r3 = __ldg(&g_src[j + 3]);
        float s0 = __ldg(&g_dinv[r0]);
        float s1 = __ldg(&g_dinv[r1]);
        float s2 = __ldg(&g_dinv[r2]);
        float s3 = __ldg(&g_dinv[r3]);
        float4 v0 = ldh4(__ldg(&g_h[(size_t)r0 * 32 + lane]));
        float4 v1 = ldh4(__ldg(&g_h[(size_t)r1 * 32 + lane]));
        float4 v2 = ldh4(__ldg(&g_h[(size_t)r2 * 32 + lane]));
        float4 v3 = ldh4(__ldg(&g_h[(size_t)r3 * 32 + lane]));
        acc.x += s0 * v0.x + s1 * v1.x + s2 * v2.x + s3 * v3.x;
        acc.y += s0 * v0.y + s1 * v1.y + s2 * v2.y + s3 * v3.y;
        acc.z += s0 * v0.z + s1 * v1.z + s2 * v2.z + s3 * v3.z;
        acc.w += s0 * v0.w + s1 * v1.w + s2 * v2.w + s3 * v3.w;
    }
    for (; j < end; j++) {
        int r = __ldg(&g_src[j]);
        float s = __ldg(&g_dinv[r]);
        float4 v = ldh4(__ldg(&g_h[(size_t)r * 32 + lane]));
        acc.x += s * v.x; acc.y += s * v.y; acc.z += s * v.z; acc.w += s * v.w;
    }

    const float4 bb = __ldg(reinterpret_cast<const float4*>(bias) + lane);
    float4 o;
    o.x = acc.x * dc + bb.x;
    o.y = acc.y * dc + bb.y;
    o.z = acc.z * dc + bb.z;
    o.w = acc.w * dc + bb.w;
    reinterpret_cast<float4*>(out + (size_t)c * HIDDIM)[lane] = o;
}

// ---------------------------------------------------------------------------
// launch — kernels only, no runtime API calls
// ---------------------------------------------------------------------------
extern "C" void kernel_launch(void* const* d_in, const int* in_sizes, int n_in,
                              void* d_out, int out_size)
{
    const float* x  = (const float*)d_in[0];
    const int*   ei = (const int*)d_in[1];       // int32 edge index
    const float* W1 = (const float*)d_in[2];
    const float* b1 = (const float*)d_in[3];
    const float* W2 = (const float*)d_in[4];
    const float* b2 = (const float*)d_in[5];
    const float* Wp = (const float*)d_in[6];
    const float* bp = (const float*)d_in[7];

    int N = in_sizes[0] / INDIM;          // 100000
    int E = in_sizes[1] / 2;              // 1600000

    float* z    = (float*)d_out;                       // z2 [N,128]
    float* proj = z + (size_t)N * HIDDIM;              // projection

    const int T = 256;
    int nBlocksN    = (N + T - 1) / T;
    int nBlocksE    = (E + T - 1) / T;
    int nBlocksGemm = (N + 127) / 128;
    int nBlocksWarp = (N + 7) / 8;
    int nScanBlocks = (N + 1023) / 1024;

    // ---- preprocessing: degrees, dinv, CSR by target, weight splits ----
    zero_deg_kernel<<<nBlocksN, T>>>(N);
    count_deg_kernel<<<nBlocksE, T>>>(ei, E);
    dinv_kernel<<<nBlocksN, T>>>(N);
    scanA_kernel<<<nScanBlocks, 1024>>>(N);
    scanB_kernel<<<1, 128>>>(nScanBlocks);
    scanC_kernel<<<nScanBlocks, 1024>>>(N);
    scatter_kernel<<<nBlocksE, T>>>(ei, E);
    convert_w_kernel<<<65536 / T, T>>>(W1, W2, Wp);

    // layer 1: h(fp16) = x @ W1 ; z1 = csr_agg(h) + b1
    gemm_tc_kernel<<<nBlocksGemm, T>>>(x, 0, WOFF_W1, nullptr, 0, nullptr, 1, N, INDIM);
    csr_agg_kernel<<<nBlocksWarp, T>>>(b1, nullptr, OFF_Z1, N);

    // layer 2: h(fp16) = z1 @ W2 ; z = csr_agg(h) + b2  (into d_out)
    gemm_tc_kernel<<<nBlocksGemm, T>>>(nullptr, OFF_Z1, WOFF_W2, nullptr, 0, nullptr, 1, N, HIDDIM);
    csr_agg_kernel<<<nBlocksWarp, T>>>(b2, z, 0, N);

    // projection head: proj = z @ Wp + bp  (fp32 out)
    gemm_tc_kernel<<<nBlocksGemm, T>>>(z, 0, WOFF_WP, proj, 0, bp, 0, N, HIDDIM);
}